// round 5
// baseline (speedup 1.0000x reference)
#include <cuda_runtime.h>
#include <cuda_bf16.h>
#include <cstdint>
#include <cstddef>

// ---------------------------------------------------------------------------
// STDP delta_w:
//   delta_w = sum_t O_t^T P_t  -  s[:,None] * W
// GEMM: K = T*B = 1024, M = POST = 4096, N = PRE = 4096, HMMA mma.sync.
// R5: gmem PRE-SWIZZLE (swizzle applied when prep writes g_A/g_B, so mainloop
// loads are fully linear: smem = stage + tid*16 + i*2048, gmem = ptr + const)
// + incremental gmem pointers. Targets R4's alu=25.8% address-math overhead.
// ---------------------------------------------------------------------------

namespace {
constexpr int T_STEPS = 64;
constexpr int BATCH   = 16;
constexpr int PRE_N   = 4096;
constexpr int POST_N  = 4096;
constexpr int KDIM    = T_STEPS * BATCH;  // 1024

constexpr int TM = 128;
constexpr int TN = 128;
constexpr int KC = 64;                       // K elems per chunk (128 B rows)
constexpr int NCHUNK  = KDIM / KC;           // 16
constexpr int A_STAGE_BYTES = TM * 128;      // 16384
constexpr int B_STAGE_BYTES = TN * 128;      // 16384
constexpr int STAGE_BYTES   = A_STAGE_BYTES + B_STAGE_BYTES;   // 32768
constexpr int SMEM_TOTAL    = 2 * STAGE_BYTES;                 // 65536

constexpr int NB_PRE  = (BATCH * PRE_N)  / 256;  // 256
constexpr int NB_POST = (BATCH * POST_N) / 256;  // 256
}

// Scratch (device globals: allocation-free rule).
// Layout: [row][chunk b][block j] where 16B block j holds logical block
// i = j ^ (row & 7)  (SW128 pre-applied so GEMM-side copies are linear).
__device__ __nv_bfloat16 g_A[POST_N * KDIM];   // out_spikes^T bf16
__device__ __nv_bfloat16 g_B[PRE_N * KDIM];    // trace_pre^T bf16
__device__ float g_spart[BATCH * POST_N];

// ---------------------------------------------------------------------------
// Combined preprocess (one launch), pre-swizzled stores.
// Each thread handles (row, b): writes 8 x 16B blocks of chunk b.
// ---------------------------------------------------------------------------
__global__ void __launch_bounds__(256) prep_kernel(
    const float* __restrict__ in_spikes, const float* __restrict__ out_spikes)
{
    if (blockIdx.x < NB_PRE) {
        int g = blockIdx.x * 256 + threadIdx.x;
        int p = g & (PRE_N - 1);
        int b = g >> 12;
        const float* src = in_spikes + (size_t)b * PRE_N + p;
        float tp = 0.0f;
        unsigned int packed[T_STEPS / 2];
#pragma unroll
        for (int t2 = 0; t2 < T_STEPS / 2; ++t2) {
            float i0 = src[(size_t)(2 * t2)     * (BATCH * PRE_N)];
            float i1 = src[(size_t)(2 * t2 + 1) * (BATCH * PRE_N)];
            tp = fminf(fmaxf(fmaf(0.5f, tp, i0), 0.0f), 1.0f);
            float v0 = tp;
            tp = fminf(fmaxf(fmaf(0.5f, tp, i1), 0.0f), 1.0f);
            float v1 = tp;
            __nv_bfloat162 h2 = __floats2bfloat162_rn(v0, v1);
            packed[t2] = *reinterpret_cast<unsigned int*>(&h2);
        }
        uint4* dst = reinterpret_cast<uint4*>(g_B + (size_t)p * KDIM + b * T_STEPS);
        const int x = p & 7;
#pragma unroll
        for (int i = 0; i < 8; ++i)
            dst[i ^ x] = make_uint4(packed[4*i+0], packed[4*i+1], packed[4*i+2], packed[4*i+3]);
    } else {
        int g = (blockIdx.x - NB_PRE) * 256 + threadIdx.x;
        int q = g & (POST_N - 1);
        int b = g >> 12;
        const float* src = out_spikes + (size_t)b * POST_N + q;
        float tp = 0.0f, sacc = 0.0f;
        unsigned int packed[T_STEPS / 2];
#pragma unroll
        for (int t2 = 0; t2 < T_STEPS / 2; ++t2) {
            float o0 = src[(size_t)(2 * t2)     * (BATCH * POST_N)];
            float o1 = src[(size_t)(2 * t2 + 1) * (BATCH * POST_N)];
            tp = fmaf(0.5f, tp, o0);
            sacc = fmaf(o0, tp, sacc);
            float w0 = o0;
            tp = fmaf(0.5f, tp, o1);
            sacc = fmaf(o1, tp, sacc);
            __nv_bfloat162 h2 = __floats2bfloat162_rn(w0, o1);
            packed[t2] = *reinterpret_cast<unsigned int*>(&h2);
        }
        uint4* dst = reinterpret_cast<uint4*>(g_A + (size_t)q * KDIM + b * T_STEPS);
        const int x = q & 7;
#pragma unroll
        for (int i = 0; i < 8; ++i)
            dst[i ^ x] = make_uint4(packed[4*i+0], packed[4*i+1], packed[4*i+2], packed[4*i+3]);
        g_spart[b * POST_N + q] = sacc;
    }
}

// ---------------------------------------------------------------------------
// PTX helpers
// ---------------------------------------------------------------------------
__device__ __forceinline__ void cp_async16(unsigned int saddr, const void* gptr) {
    asm volatile("cp.async.cg.shared.global [%0], [%1], 16;"
                 :: "r"(saddr), "l"(gptr) : "memory");
}

__device__ __forceinline__ void ldsm_x4(unsigned int& r0, unsigned int& r1,
                                        unsigned int& r2, unsigned int& r3,
                                        unsigned int addr) {
    asm volatile("ldmatrix.sync.aligned.m8n8.x4.shared.b16 {%0,%1,%2,%3}, [%4];"
                 : "=r"(r0), "=r"(r1), "=r"(r2), "=r"(r3) : "r"(addr));
}

__device__ __forceinline__ void mma16816(float* c,
                                         unsigned int a0, unsigned int a1,
                                         unsigned int a2, unsigned int a3,
                                         unsigned int b0, unsigned int b1) {
    asm volatile(
        "mma.sync.aligned.m16n8k16.row.col.f32.bf16.bf16.f32 "
        "{%0,%1,%2,%3}, {%4,%5,%6,%7}, {%8,%9}, {%0,%1,%2,%3};"
        : "+f"(c[0]), "+f"(c[1]), "+f"(c[2]), "+f"(c[3])
        : "r"(a0), "r"(a1), "r"(a2), "r"(a3), "r"(b0), "r"(b1));
}

// ---------------------------------------------------------------------------
// GEMM: D[128 x 128] tile, 4 warps (2 M x 2 N), warp tile 64x64,
// 2-stage pipeline, 3 CTAs/SM, linear loads (pre-swizzled gmem).
// Fused epilogue: out = acc - s[m] * W[m][n], s reduced from g_spart inline.
// ---------------------------------------------------------------------------
__global__ void __launch_bounds__(128, 3) stdp_gemm_kernel(
    const float* __restrict__ weight, float* __restrict__ out)
{
    extern __shared__ __align__(1024) char smem[];
    const unsigned int sbase = (unsigned int)__cvta_generic_to_shared(smem);
    const int tid = threadIdx.x;
    const int wid = tid >> 5;
    const int lid = tid & 31;
    const int n0 = blockIdx.x * TN;
    const int m0 = blockIdx.y * TM;

    const int warp_m = wid & 1;   // m offset 0/64
    const int warp_n = wid >> 1;  // n offset 0/64

    // per-thread linear load pointers (advanced by KC elems per chunk)
    const __nv_bfloat16* pa = g_A + (size_t)(m0 + (tid >> 3)) * KDIM + (tid & 7) * 8;
    const __nv_bfloat16* pb = g_B + (size_t)(n0 + (tid >> 3)) * KDIM + (tid & 7) * 8;
    const unsigned int s_tid = sbase + (unsigned int)tid * 16;

    // linear loader: rows advance 16 per i; smem is plain row-major (the data
    // itself is pre-swizzled in gmem, so this reproduces the SW128 layout).
    auto load_chunk = [&](const __nv_bfloat16* a, const __nv_bfloat16* b, int st) {
        const unsigned int sa = s_tid + st * STAGE_BYTES;
#pragma unroll
        for (int i = 0; i < 8; ++i)
            cp_async16(sa + i * 2048, a + (size_t)i * 16 * KDIM);
        const unsigned int sb = sa + A_STAGE_BYTES;
#pragma unroll
        for (int i = 0; i < 8; ++i)
            cp_async16(sb + i * 2048, b + (size_t)i * 16 * KDIM);
    };

    // ---- ldmatrix lane addressing (reads the swizzled layout) ----
    const int q  = lid >> 3;
    const int r  = lid & 7;
    const int lrow = (q & 1) * 8 + r;
    const int lkb  = (q >> 1) * 16;
    unsigned int kxor[4];
#pragma unroll
    for (int ks = 0; ks < 4; ++ks)
        kxor[ks] = (unsigned int)((ks * 32 + lkb) ^ (r << 4));
    const unsigned int a_rowbase = (unsigned int)((warp_m * 64 + lrow) * 128);
    const unsigned int b_rowbase = (unsigned int)((warp_n * 64 + lrow) * 128);

    float acc[4][8][4];
#pragma unroll
    for (int mt = 0; mt < 4; ++mt)
#pragma unroll
        for (int nt = 0; nt < 8; ++nt)
#pragma unroll
            for (int j = 0; j < 4; ++j) acc[mt][nt][j] = 0.0f;

    unsigned int af[2][4][4], bf[2][4][4];

    // ---- prologue ----
    load_chunk(pa, pb, 0);
    asm volatile("cp.async.commit_group;" ::: "memory");
    pa += KC; pb += KC;

    int st = 0;
    // ---- mainloop ----
    for (int c = 0; c < NCHUNK; ++c) {
        asm volatile("cp.async.wait_group 0;" ::: "memory");
        __syncthreads();   // chunk c visible; all warps done reading st^1

        if (c + 1 < NCHUNK) {
            load_chunk(pa, pb, st ^ 1);
            pa += KC; pb += KC;
        }
        asm volatile("cp.async.commit_group;" ::: "memory");

        const unsigned int sa = sbase + st * STAGE_BYTES;
        const unsigned int sb = sa + A_STAGE_BYTES;
        st ^= 1;

        // preload ks=0 fragments
#pragma unroll
        for (int mt = 0; mt < 4; ++mt)
            ldsm_x4(af[0][mt][0], af[0][mt][1], af[0][mt][2], af[0][mt][3],
                    sa + a_rowbase + mt * 2048 + kxor[0]);
#pragma unroll
        for (int nt2 = 0; nt2 < 4; ++nt2)
            ldsm_x4(bf[0][nt2][0], bf[0][nt2][1], bf[0][nt2][2], bf[0][nt2][3],
                    sb + b_rowbase + nt2 * 2048 + kxor[0]);

#pragma unroll
        for (int ks = 0; ks < 4; ++ks) {
            const int cur = ks & 1, nxt = cur ^ 1;
            if (ks < 3) {
#pragma unroll
                for (int mt = 0; mt < 4; ++mt)
                    ldsm_x4(af[nxt][mt][0], af[nxt][mt][1], af[nxt][mt][2], af[nxt][mt][3],
                            sa + a_rowbase + mt * 2048 + kxor[ks + 1]);
#pragma unroll
                for (int nt2 = 0; nt2 < 4; ++nt2)
                    ldsm_x4(bf[nxt][nt2][0], bf[nxt][nt2][1], bf[nxt][nt2][2], bf[nxt][nt2][3],
                            sb + b_rowbase + nt2 * 2048 + kxor[ks + 1]);
            }
#pragma unroll
            for (int mt = 0; mt < 4; ++mt)
#pragma unroll
                for (int nt2 = 0; nt2 < 4; ++nt2) {
                    mma16816(acc[mt][2 * nt2],
                             af[cur][mt][0], af[cur][mt][1], af[cur][mt][2], af[cur][mt][3],
                             bf[cur][nt2][0], bf[cur][nt2][2]);
                    mma16816(acc[mt][2 * nt2 + 1],
                             af[cur][mt][0], af[cur][mt][1], af[cur][mt][2], af[cur][mt][3],
                             bf[cur][nt2][1], bf[cur][nt2][3]);
                }
        }
    }

    // ---- fused epilogue: out = acc - s[m] * W[m][n]; s from g_spart ----
    const int tid4 = lid >> 2;
    const int tp   = lid & 3;
#pragma unroll
    for (int mt = 0; mt < 4; ++mt) {
#pragma unroll
        for (int half = 0; half < 2; ++half) {
            const int gm = m0 + warp_m * 64 + mt * 16 + half * 8 + tid4;
            float sv = 0.0f;
#pragma unroll
            for (int b = 0; b < BATCH; ++b) sv += g_spart[b * POST_N + gm];
            const float* wrow = weight + (size_t)gm * PRE_N + n0 + warp_n * 64;
            float* orow       = out    + (size_t)gm * PRE_N + n0 + warp_n * 64;
#pragma unroll
            for (int nt = 0; nt < 8; ++nt) {
                const int col = nt * 8 + 2 * tp;
                float2 w2 = *reinterpret_cast<const float2*>(wrow + col);
                float2 o2;
                o2.x = acc[mt][nt][2 * half + 0] - sv * w2.x;
                o2.y = acc[mt][nt][2 * half + 1] - sv * w2.y;
                *reinterpret_cast<float2*>(orow + col) = o2;
            }
        }
    }
}

// ---------------------------------------------------------------------------
extern "C" void kernel_launch(void* const* d_in, const int* in_sizes, int n_in,
                              void* d_out, int out_size) {
    (void)in_sizes; (void)n_in; (void)out_size;
    const float* in_spikes  = (const float*)d_in[0];
    const float* out_spikes = (const float*)d_in[1];
    const float* weight     = (const float*)d_in[2];
    float* out = (float*)d_out;

    cudaFuncSetAttribute(stdp_gemm_kernel,
                         cudaFuncAttributeMaxDynamicSharedMemorySize, SMEM_TOTAL);

    prep_kernel<<<NB_PRE + NB_POST, 256>>>(in_spikes, out_spikes);

    dim3 grid(PRE_N / TN, POST_N / TM);
    stdp_gemm_kernel<<<grid, 128, SMEM_TOTAL>>>(weight, out);
}

// round 6
// speedup vs baseline: 1.0876x; 1.0876x over previous
#include <cuda_runtime.h>
#include <cuda_bf16.h>
#include <cstdint>
#include <cstddef>

// ---------------------------------------------------------------------------
// STDP delta_w:
//   delta_w = sum_t O_t^T P_t  -  s[:,None] * W
// GEMM: K = T*B = 1024, M = POST = 4096, N = PRE = 4096, HMMA mma.sync.
// R6: 16 warps/SM. 2 CTAs x 256 threads, CTA tile 128x128, 8 warps (2M x 4N),
// warp tile 64x32 (64 acc regs), single-buffered fragments, 2-stage cp.async.
// R4/R5 showed 12 warps latency-bound at tensor ~47%, all pipes < 52% —
// register file (128 acc) was the warp cap; smaller warp tile trades 1.25x
// LDSM traffic for 4 warps/SMSP of latency hiding.
// ---------------------------------------------------------------------------

namespace {
constexpr int T_STEPS = 64;
constexpr int BATCH   = 16;
constexpr int PRE_N   = 4096;
constexpr int POST_N  = 4096;
constexpr int KDIM    = T_STEPS * BATCH;  // 1024

constexpr int TM = 128;
constexpr int TN = 128;
constexpr int KC = 64;                       // K elems per chunk (128 B rows)
constexpr int NCHUNK  = KDIM / KC;           // 16
constexpr int A_STAGE_BYTES = TM * 128;      // 16384
constexpr int B_STAGE_BYTES = TN * 128;      // 16384
constexpr int STAGE_BYTES   = A_STAGE_BYTES + B_STAGE_BYTES;   // 32768
constexpr int SMEM_TOTAL    = 2 * STAGE_BYTES;                 // 65536

constexpr int NB_PRE  = (BATCH * PRE_N)  / 256;  // 256
constexpr int NB_POST = (BATCH * POST_N) / 256;  // 256
}

// Scratch (device globals: allocation-free rule)
__device__ __nv_bfloat16 g_A[POST_N * KDIM];   // out_spikes^T bf16 [post][k]
__device__ __nv_bfloat16 g_B[PRE_N * KDIM];    // trace_pre^T bf16 [pre][k]
__device__ float g_spart[BATCH * POST_N];

// ---------------------------------------------------------------------------
// Combined preprocess (one launch):
//  blocks [0, NB_PRE)             : trace_pre scan -> g_B (K-major bf16)
//  blocks [NB_PRE, NB_PRE+NB_POST): out_spikes^T   -> g_A + s partials
// ---------------------------------------------------------------------------
__global__ void __launch_bounds__(256) prep_kernel(
    const float* __restrict__ in_spikes, const float* __restrict__ out_spikes)
{
    if (blockIdx.x < NB_PRE) {
        int g = blockIdx.x * 256 + threadIdx.x;
        int p = g & (PRE_N - 1);
        int b = g >> 12;
        const float* src = in_spikes + (size_t)b * PRE_N + p;
        float tp = 0.0f;
        unsigned int packed[T_STEPS / 2];
#pragma unroll
        for (int t2 = 0; t2 < T_STEPS / 2; ++t2) {
            float i0 = src[(size_t)(2 * t2)     * (BATCH * PRE_N)];
            float i1 = src[(size_t)(2 * t2 + 1) * (BATCH * PRE_N)];
            tp = fminf(fmaxf(fmaf(0.5f, tp, i0), 0.0f), 1.0f);
            float v0 = tp;
            tp = fminf(fmaxf(fmaf(0.5f, tp, i1), 0.0f), 1.0f);
            float v1 = tp;
            __nv_bfloat162 h2 = __floats2bfloat162_rn(v0, v1);
            packed[t2] = *reinterpret_cast<unsigned int*>(&h2);
        }
        uint4* dst = reinterpret_cast<uint4*>(g_B + (size_t)p * KDIM + b * T_STEPS);
#pragma unroll
        for (int i = 0; i < 8; ++i)
            dst[i] = make_uint4(packed[4*i+0], packed[4*i+1], packed[4*i+2], packed[4*i+3]);
    } else {
        int g = (blockIdx.x - NB_PRE) * 256 + threadIdx.x;
        int q = g & (POST_N - 1);
        int b = g >> 12;
        const float* src = out_spikes + (size_t)b * POST_N + q;
        float tp = 0.0f, sacc = 0.0f;
        unsigned int packed[T_STEPS / 2];
#pragma unroll
        for (int t2 = 0; t2 < T_STEPS / 2; ++t2) {
            float o0 = src[(size_t)(2 * t2)     * (BATCH * POST_N)];
            float o1 = src[(size_t)(2 * t2 + 1) * (BATCH * POST_N)];
            tp = fmaf(0.5f, tp, o0);
            sacc = fmaf(o0, tp, sacc);
            float w0 = o0;
            tp = fmaf(0.5f, tp, o1);
            sacc = fmaf(o1, tp, sacc);
            __nv_bfloat162 h2 = __floats2bfloat162_rn(w0, o1);
            packed[t2] = *reinterpret_cast<unsigned int*>(&h2);
        }
        uint4* dst = reinterpret_cast<uint4*>(g_A + (size_t)q * KDIM + b * T_STEPS);
#pragma unroll
        for (int i = 0; i < 8; ++i)
            dst[i] = make_uint4(packed[4*i+0], packed[4*i+1], packed[4*i+2], packed[4*i+3]);
        g_spart[b * POST_N + q] = sacc;
    }
}

// ---------------------------------------------------------------------------
// PTX helpers
// ---------------------------------------------------------------------------
__device__ __forceinline__ void cp_async16(unsigned int saddr, const void* gptr) {
    asm volatile("cp.async.cg.shared.global [%0], [%1], 16;"
                 :: "r"(saddr), "l"(gptr) : "memory");
}

__device__ __forceinline__ void ldsm_x4(unsigned int& r0, unsigned int& r1,
                                        unsigned int& r2, unsigned int& r3,
                                        unsigned int addr) {
    asm volatile("ldmatrix.sync.aligned.m8n8.x4.shared.b16 {%0,%1,%2,%3}, [%4];"
                 : "=r"(r0), "=r"(r1), "=r"(r2), "=r"(r3) : "r"(addr));
}

__device__ __forceinline__ void mma16816(float* c,
                                         unsigned int a0, unsigned int a1,
                                         unsigned int a2, unsigned int a3,
                                         unsigned int b0, unsigned int b1) {
    asm volatile(
        "mma.sync.aligned.m16n8k16.row.col.f32.bf16.bf16.f32 "
        "{%0,%1,%2,%3}, {%4,%5,%6,%7}, {%8,%9}, {%0,%1,%2,%3};"
        : "+f"(c[0]), "+f"(c[1]), "+f"(c[2]), "+f"(c[3])
        : "r"(a0), "r"(a1), "r"(a2), "r"(a3), "r"(b0), "r"(b1));
}

// ---------------------------------------------------------------------------
// GEMM: D[128 x 128] CTA tile, 8 warps (2 M x 4 N), warp tile 64x32,
// 2-stage cp.async pipeline, 2 CTAs/SM (16 warps/SM).
// Fused epilogue: out = acc - s[m] * W[m][n], s reduced from g_spart inline.
// ---------------------------------------------------------------------------
__global__ void __launch_bounds__(256, 2) stdp_gemm_kernel(
    const float* __restrict__ weight, float* __restrict__ out)
{
    extern __shared__ __align__(1024) char smem[];
    const unsigned int sbase = (unsigned int)__cvta_generic_to_shared(smem);
    const int tid = threadIdx.x;
    const int wid = tid >> 5;
    const int lid = tid & 31;
    const int n0 = blockIdx.x * TN;
    const int m0 = blockIdx.y * TM;

    const int warp_m = wid & 1;   // m offset 0/64
    const int warp_n = wid >> 1;  // n offset 0/32/64/96

    const __nv_bfloat16* gA = g_A + (size_t)m0 * KDIM;
    const __nv_bfloat16* gB = g_B + (size_t)n0 * KDIM;

    // ---- async tile loader (256 threads; A+B = 2048 x 16B ops) ----
    auto load_chunk = [&](int c, int st) {
        unsigned int sa = sbase + st * STAGE_BYTES;
        unsigned int sb = sa + A_STAGE_BYTES;
#pragma unroll
        for (int i = 0; i < 4; ++i) {
            int idx = tid + i * 256;
            int m = idx >> 3, k8 = idx & 7;
            unsigned int sw = (unsigned int)(m * 128) + ((unsigned int)(k8 * 16) ^ ((m & 7) << 4));
            cp_async16(sa + sw, gA + (size_t)m * KDIM + c * KC + k8 * 8);
        }
#pragma unroll
        for (int i = 0; i < 4; ++i) {
            int idx = tid + i * 256;
            int n = idx >> 3, k8 = idx & 7;
            unsigned int sw = (unsigned int)(n * 128) + ((unsigned int)(k8 * 16) ^ ((n & 7) << 4));
            cp_async16(sb + sw, gB + (size_t)n * KDIM + c * KC + k8 * 8);
        }
    };

    // ---- ldmatrix lane addressing ----
    const int q  = lid >> 3;
    const int r  = lid & 7;
    const int lrow = (q & 1) * 8 + r;
    const int lkb  = (q >> 1) * 16;
    unsigned int kxor[4];
#pragma unroll
    for (int ks = 0; ks < 4; ++ks)
        kxor[ks] = (unsigned int)((ks * 32 + lkb) ^ (r << 4));
    const unsigned int a_rowbase = (unsigned int)((warp_m * 64 + lrow) * 128);
    const unsigned int b_rowbase = (unsigned int)((warp_n * 32 + lrow) * 128);

    float acc[4][4][4];
#pragma unroll
    for (int mt = 0; mt < 4; ++mt)
#pragma unroll
        for (int nt = 0; nt < 4; ++nt)
#pragma unroll
            for (int j = 0; j < 4; ++j) acc[mt][nt][j] = 0.0f;

    // ---- prologue: stage 0 ----
    load_chunk(0, 0);
    asm volatile("cp.async.commit_group;" ::: "memory");

    int st = 0;
    // ---- mainloop ----
    for (int c = 0; c < NCHUNK; ++c) {
        asm volatile("cp.async.wait_group 0;" ::: "memory");
        __syncthreads();   // chunk c visible; all warps done reading st^1

        if (c + 1 < NCHUNK) load_chunk(c + 1, st ^ 1);
        asm volatile("cp.async.commit_group;" ::: "memory");

        const unsigned int sa = sbase + st * STAGE_BYTES;
        const unsigned int sb = sa + A_STAGE_BYTES;
        st ^= 1;

#pragma unroll
        for (int ks = 0; ks < 4; ++ks) {
            unsigned int af[4][4], bf[2][4];
#pragma unroll
            for (int mt = 0; mt < 4; ++mt)
                ldsm_x4(af[mt][0], af[mt][1], af[mt][2], af[mt][3],
                        sa + a_rowbase + mt * 2048 + kxor[ks]);
#pragma unroll
            for (int nt2 = 0; nt2 < 2; ++nt2)
                ldsm_x4(bf[nt2][0], bf[nt2][1], bf[nt2][2], bf[nt2][3],
                        sb + b_rowbase + nt2 * 2048 + kxor[ks]);
#pragma unroll
            for (int mt = 0; mt < 4; ++mt)
#pragma unroll
                for (int nt2 = 0; nt2 < 2; ++nt2) {
                    mma16816(acc[mt][2 * nt2],
                             af[mt][0], af[mt][1], af[mt][2], af[mt][3],
                             bf[nt2][0], bf[nt2][2]);
                    mma16816(acc[mt][2 * nt2 + 1],
                             af[mt][0], af[mt][1], af[mt][2], af[mt][3],
                             bf[nt2][1], bf[nt2][3]);
                }
        }
    }

    // ---- fused epilogue: out = acc - s[m] * W[m][n]; s from g_spart ----
    const int tid4 = lid >> 2;
    const int tp   = lid & 3;
#pragma unroll
    for (int mt = 0; mt < 4; ++mt) {
#pragma unroll
        for (int half = 0; half < 2; ++half) {
            const int gm = m0 + warp_m * 64 + mt * 16 + half * 8 + tid4;
            float sv = 0.0f;
#pragma unroll
            for (int b = 0; b < BATCH; ++b) sv += g_spart[b * POST_N + gm];
            const float* wrow = weight + (size_t)gm * PRE_N + n0 + warp_n * 32;
            float* orow       = out    + (size_t)gm * PRE_N + n0 + warp_n * 32;
#pragma unroll
            for (int nt = 0; nt < 4; ++nt) {
                const int col = nt * 8 + 2 * tp;
                float2 w2 = *reinterpret_cast<const float2*>(wrow + col);
                float2 o2;
                o2.x = acc[mt][nt][2 * half + 0] - sv * w2.x;
                o2.y = acc[mt][nt][2 * half + 1] - sv * w2.y;
                *reinterpret_cast<float2*>(orow + col) = o2;
            }
        }
    }
}

// ---------------------------------------------------------------------------
extern "C" void kernel_launch(void* const* d_in, const int* in_sizes, int n_in,
                              void* d_out, int out_size) {
    (void)in_sizes; (void)n_in; (void)out_size;
    const float* in_spikes  = (const float*)d_in[0];
    const float* out_spikes = (const float*)d_in[1];
    const float* weight     = (const float*)d_in[2];
    float* out = (float*)d_out;

    cudaFuncSetAttribute(stdp_gemm_kernel,
                         cudaFuncAttributeMaxDynamicSharedMemorySize, SMEM_TOTAL);

    prep_kernel<<<NB_PRE + NB_POST, 256>>>(in_spikes, out_spikes);

    dim3 grid(PRE_N / TN, POST_N / TM);
    stdp_gemm_kernel<<<grid, 256, SMEM_TOTAL>>>(weight, out);
}

// round 7
// speedup vs baseline: 1.1263x; 1.0355x over previous
#include <cuda_runtime.h>
#include <cuda_bf16.h>
#include <cstdint>
#include <cstddef>

// ---------------------------------------------------------------------------
// STDP delta_w:
//   delta_w = sum_t O_t^T P_t  -  s[:,None] * W
// GEMM: K = T*B = 1024, M = POST = 4096, N = PRE = 4096, HMMA mma.sync.
// R7: 16 warps/SM kept (2 CTAs x 256 thr, warp tile 64x32). 3-stage cp.async
// pipeline (wait_group 1) + cp.async issue spread across the ks loop (2/ks)
// + incremental gmem pointers. Targets the per-chunk post-barrier load-issue
// bubble that pinned tensor at ~51% in R6.
// ---------------------------------------------------------------------------

namespace {
constexpr int T_STEPS = 64;
constexpr int BATCH   = 16;
constexpr int PRE_N   = 4096;
constexpr int POST_N  = 4096;
constexpr int KDIM    = T_STEPS * BATCH;  // 1024

constexpr int TM = 128;
constexpr int TN = 128;
constexpr int KC = 64;                       // K elems per chunk (128 B rows)
constexpr int NCHUNK  = KDIM / KC;           // 16
constexpr int NSTAGES = 3;
constexpr int A_STAGE_BYTES = TM * 128;      // 16384
constexpr int B_STAGE_BYTES = TN * 128;      // 16384
constexpr int STAGE_BYTES   = A_STAGE_BYTES + B_STAGE_BYTES;   // 32768
constexpr int SMEM_TOTAL    = NSTAGES * STAGE_BYTES;           // 98304

constexpr int NB_PRE  = (BATCH * PRE_N)  / 256;  // 256
constexpr int NB_POST = (BATCH * POST_N) / 256;  // 256
}

// Scratch (device globals: allocation-free rule)
__device__ __nv_bfloat16 g_A[POST_N * KDIM];   // out_spikes^T bf16 [post][k]
__device__ __nv_bfloat16 g_B[PRE_N * KDIM];    // trace_pre^T bf16 [pre][k]
__device__ float g_spart[BATCH * POST_N];

// ---------------------------------------------------------------------------
// Combined preprocess (one launch):
//  blocks [0, NB_PRE)             : trace_pre scan -> g_B (K-major bf16)
//  blocks [NB_PRE, NB_PRE+NB_POST): out_spikes^T   -> g_A + s partials
// ---------------------------------------------------------------------------
__global__ void __launch_bounds__(256) prep_kernel(
    const float* __restrict__ in_spikes, const float* __restrict__ out_spikes)
{
    if (blockIdx.x < NB_PRE) {
        int g = blockIdx.x * 256 + threadIdx.x;
        int p = g & (PRE_N - 1);
        int b = g >> 12;
        const float* src = in_spikes + (size_t)b * PRE_N + p;
        float tp = 0.0f;
        unsigned int packed[T_STEPS / 2];
#pragma unroll
        for (int t2 = 0; t2 < T_STEPS / 2; ++t2) {
            float i0 = src[(size_t)(2 * t2)     * (BATCH * PRE_N)];
            float i1 = src[(size_t)(2 * t2 + 1) * (BATCH * PRE_N)];
            tp = fminf(fmaxf(fmaf(0.5f, tp, i0), 0.0f), 1.0f);
            float v0 = tp;
            tp = fminf(fmaxf(fmaf(0.5f, tp, i1), 0.0f), 1.0f);
            float v1 = tp;
            __nv_bfloat162 h2 = __floats2bfloat162_rn(v0, v1);
            packed[t2] = *reinterpret_cast<unsigned int*>(&h2);
        }
        uint4* dst = reinterpret_cast<uint4*>(g_B + (size_t)p * KDIM + b * T_STEPS);
#pragma unroll
        for (int i = 0; i < 8; ++i)
            dst[i] = make_uint4(packed[4*i+0], packed[4*i+1], packed[4*i+2], packed[4*i+3]);
    } else {
        int g = (blockIdx.x - NB_PRE) * 256 + threadIdx.x;
        int q = g & (POST_N - 1);
        int b = g >> 12;
        const float* src = out_spikes + (size_t)b * POST_N + q;
        float tp = 0.0f, sacc = 0.0f;
        unsigned int packed[T_STEPS / 2];
#pragma unroll
        for (int t2 = 0; t2 < T_STEPS / 2; ++t2) {
            float o0 = src[(size_t)(2 * t2)     * (BATCH * POST_N)];
            float o1 = src[(size_t)(2 * t2 + 1) * (BATCH * POST_N)];
            tp = fmaf(0.5f, tp, o0);
            sacc = fmaf(o0, tp, sacc);
            float w0 = o0;
            tp = fmaf(0.5f, tp, o1);
            sacc = fmaf(o1, tp, sacc);
            __nv_bfloat162 h2 = __floats2bfloat162_rn(w0, o1);
            packed[t2] = *reinterpret_cast<unsigned int*>(&h2);
        }
        uint4* dst = reinterpret_cast<uint4*>(g_A + (size_t)q * KDIM + b * T_STEPS);
#pragma unroll
        for (int i = 0; i < 8; ++i)
            dst[i] = make_uint4(packed[4*i+0], packed[4*i+1], packed[4*i+2], packed[4*i+3]);
        g_spart[b * POST_N + q] = sacc;
    }
}

// ---------------------------------------------------------------------------
// PTX helpers
// ---------------------------------------------------------------------------
__device__ __forceinline__ void cp_async16(unsigned int saddr, const void* gptr) {
    asm volatile("cp.async.cg.shared.global [%0], [%1], 16;"
                 :: "r"(saddr), "l"(gptr) : "memory");
}

__device__ __forceinline__ void ldsm_x4(unsigned int& r0, unsigned int& r1,
                                        unsigned int& r2, unsigned int& r3,
                                        unsigned int addr) {
    asm volatile("ldmatrix.sync.aligned.m8n8.x4.shared.b16 {%0,%1,%2,%3}, [%4];"
                 : "=r"(r0), "=r"(r1), "=r"(r2), "=r"(r3) : "r"(addr));
}

__device__ __forceinline__ void mma16816(float* c,
                                         unsigned int a0, unsigned int a1,
                                         unsigned int a2, unsigned int a3,
                                         unsigned int b0, unsigned int b1) {
    asm volatile(
        "mma.sync.aligned.m16n8k16.row.col.f32.bf16.bf16.f32 "
        "{%0,%1,%2,%3}, {%4,%5,%6,%7}, {%8,%9}, {%0,%1,%2,%3};"
        : "+f"(c[0]), "+f"(c[1]), "+f"(c[2]), "+f"(c[3])
        : "r"(a0), "r"(a1), "r"(a2), "r"(a3), "r"(b0), "r"(b1));
}

// ---------------------------------------------------------------------------
// GEMM: D[128 x 128] CTA tile, 8 warps (2 M x 4 N), warp tile 64x32,
// 3-stage cp.async pipeline (wait_group 1), 2 CTAs/SM (16 warps/SM).
// cp.async issues interleaved into the ks loop (2 per ks).
// Fused epilogue: out = acc - s[m] * W[m][n], s reduced from g_spart inline.
// ---------------------------------------------------------------------------
__global__ void __launch_bounds__(256, 2) stdp_gemm_kernel(
    const float* __restrict__ weight, float* __restrict__ out)
{
    extern __shared__ __align__(1024) char smem[];
    const unsigned int sbase = (unsigned int)__cvta_generic_to_shared(smem);
    const int tid = threadIdx.x;
    const int wid = tid >> 5;
    const int lid = tid & 31;
    const int n0 = blockIdx.x * TN;
    const int m0 = blockIdx.y * TM;

    const int warp_m = wid & 1;   // m offset 0/64
    const int warp_n = wid >> 1;  // n offset 0/32/64/96

    // ---- per-thread load addressing ----
    // op i (i=0..3) covers rows (tid>>3) + i*32; column block k8 = tid&7.
    const int lm = tid >> 3;
    const int k8 = tid & 7;
    const unsigned int sw_base =
        (unsigned int)(lm * 128) + ((unsigned int)(k8 * 16) ^ ((lm & 7) << 4));
    // gmem pointers for chunk being prefetched (advance += KC per chunk)
    const __nv_bfloat16* pa = g_A + (size_t)(m0 + lm) * KDIM + k8 * 8;
    const __nv_bfloat16* pb = g_B + (size_t)(n0 + lm) * KDIM + k8 * 8;

    // full-chunk loader (prologue only)
    auto load_chunk_full = [&](const __nv_bfloat16* a, const __nv_bfloat16* b, int st) {
        const unsigned int sa = sbase + st * STAGE_BYTES + sw_base;
#pragma unroll
        for (int i = 0; i < 4; ++i)
            cp_async16(sa + i * 4096, a + (size_t)i * 32 * KDIM);
        const unsigned int sb = sa + A_STAGE_BYTES;
#pragma unroll
        for (int i = 0; i < 4; ++i)
            cp_async16(sb + i * 4096, b + (size_t)i * 32 * KDIM);
    };

    // ---- ldmatrix lane addressing ----
    const int q  = lid >> 3;
    const int r  = lid & 7;
    const int lrow = (q & 1) * 8 + r;
    const int lkb  = (q >> 1) * 16;
    unsigned int kxor[4];
#pragma unroll
    for (int ks = 0; ks < 4; ++ks)
        kxor[ks] = (unsigned int)((ks * 32 + lkb) ^ (r << 4));
    const unsigned int a_rowbase = (unsigned int)((warp_m * 64 + lrow) * 128);
    const unsigned int b_rowbase = (unsigned int)((warp_n * 32 + lrow) * 128);

    float acc[4][4][4];
#pragma unroll
    for (int mt = 0; mt < 4; ++mt)
#pragma unroll
        for (int nt = 0; nt < 4; ++nt)
#pragma unroll
            for (int j = 0; j < 4; ++j) acc[mt][nt][j] = 0.0f;

    // ---- prologue: load chunks 0 and 1 into stages 0 and 1 ----
    load_chunk_full(pa, pb, 0);
    asm volatile("cp.async.commit_group;" ::: "memory");
    load_chunk_full(pa + KC, pb + KC, 1);
    asm volatile("cp.async.commit_group;" ::: "memory");
    pa += 2 * KC; pb += 2 * KC;   // now point at chunk 2 (next prefetch)

    int st = 0;
    // ---- mainloop ----
    for (int c = 0; c < NCHUNK; ++c) {
        asm volatile("cp.async.wait_group 1;" ::: "memory");
        __syncthreads();   // chunk c visible; all warps done with stage st2

        const unsigned int sa = sbase + st * STAGE_BYTES;
        const unsigned int sb = sa + A_STAGE_BYTES;
        int st2 = st + 2; if (st2 >= NSTAGES) st2 -= NSTAGES;   // stage for c+2
        const unsigned int spa = sbase + st2 * STAGE_BYTES + sw_base;
        const unsigned int spb = spa + A_STAGE_BYTES;
        const bool do_load = (c + 2 < NCHUNK);

#pragma unroll
        for (int ks = 0; ks < 4; ++ks) {
            unsigned int af[4][4], bf[2][4];
#pragma unroll
            for (int mt = 0; mt < 4; ++mt)
                ldsm_x4(af[mt][0], af[mt][1], af[mt][2], af[mt][3],
                        sa + a_rowbase + mt * 2048 + kxor[ks]);
#pragma unroll
            for (int nt2 = 0; nt2 < 2; ++nt2)
                ldsm_x4(bf[nt2][0], bf[nt2][1], bf[nt2][2], bf[nt2][3],
                        sb + b_rowbase + nt2 * 2048 + kxor[ks]);

            // spread chunk-(c+2) loads: 2 cp.asyncs per ks
            if (do_load) {
                cp_async16(spa + ks * 4096, pa + (size_t)ks * 32 * KDIM);
                cp_async16(spb + ks * 4096, pb + (size_t)ks * 32 * KDIM);
            }

#pragma unroll
            for (int mt = 0; mt < 4; ++mt)
#pragma unroll
                for (int nt2 = 0; nt2 < 2; ++nt2) {
                    mma16816(acc[mt][2 * nt2],
                             af[mt][0], af[mt][1], af[mt][2], af[mt][3],
                             bf[nt2][0], bf[nt2][2]);
                    mma16816(acc[mt][2 * nt2 + 1],
                             af[mt][0], af[mt][1], af[mt][2], af[mt][3],
                             bf[nt2][1], bf[nt2][3]);
                }
        }
        asm volatile("cp.async.commit_group;" ::: "memory");
        pa += KC; pb += KC;
        if (++st == NSTAGES) st = 0;
    }

    // ---- fused epilogue: out = acc - s[m] * W[m][n]; s from g_spart ----
    const int tid4 = lid >> 2;
    const int tp   = lid & 3;
#pragma unroll
    for (int mt = 0; mt < 4; ++mt) {
#pragma unroll
        for (int half = 0; half < 2; ++half) {
            const int gm = m0 + warp_m * 64 + mt * 16 + half * 8 + tid4;
            float sv = 0.0f;
#pragma unroll
            for (int b = 0; b < BATCH; ++b) sv += g_spart[b * POST_N + gm];
            const float* wrow = weight + (size_t)gm * PRE_N + n0 + warp_n * 32;
            float* orow       = out    + (size_t)gm * PRE_N + n0 + warp_n * 32;
#pragma unroll
            for (int nt = 0; nt < 4; ++nt) {
                const int col = nt * 8 + 2 * tp;
                float2 w2 = *reinterpret_cast<const float2*>(wrow + col);
                float2 o2;
                o2.x = acc[mt][nt][2 * half + 0] - sv * w2.x;
                o2.y = acc[mt][nt][2 * half + 1] - sv * w2.y;
                *reinterpret_cast<float2*>(orow + col) = o2;
            }
        }
    }
}

// ---------------------------------------------------------------------------
extern "C" void kernel_launch(void* const* d_in, const int* in_sizes, int n_in,
                              void* d_out, int out_size) {
    (void)in_sizes; (void)n_in; (void)out_size;
    const float* in_spikes  = (const float*)d_in[0];
    const float* out_spikes = (const float*)d_in[1];
    const float* weight     = (const float*)d_in[2];
    float* out = (float*)d_out;

    cudaFuncSetAttribute(stdp_gemm_kernel,
                         cudaFuncAttributeMaxDynamicSharedMemorySize, SMEM_TOTAL);

    prep_kernel<<<NB_PRE + NB_POST, 256>>>(in_spikes, out_spikes);

    dim3 grid(PRE_N / TN, POST_N / TM);
    stdp_gemm_kernel<<<grid, 256, SMEM_TOTAL>>>(weight, out);
}